// round 7
// baseline (speedup 1.0000x reference)
#include <cuda_runtime.h>
#include <cuda_bf16.h>
#include <math.h>

// Static shapes: B=2048, D=256, K = D/2-1 = 127. Output R[2048,256,256] fp32.
// Nonzeros (even rows r only):
//   col r-2 -> sin(p*theta_{(r-2)/2})    (r >= 2)
//   col r   -> cos(p*theta_{min(r/2,126)})
//   col r+2 -> -sin(p*theta_{r/2})       (r/2 <= 126)
// theta_i = 10000^(-2*(i-1)/256)
//
// Grid: 8192 blocks = 2048 matrices x 4 chunks. Chunk q owns row-groups
// [16q, 16q+16) (group = 4 rows = 256 quads). Thread tid = h*64+j writes quad
// (kp*256 + tid) for each kp in the chunk. R7: the <=2 quads this thread will
// patch are SKIPPED in the zero loop (no double write) and written exactly
// once in the patch phase.

#define K_ITERS 127

__global__ __launch_bounds__(256) void rope_kernel(float4* __restrict__ out) {
    // Table slice: indices i = off + t, t in [0,36), off = 2*k0 - 1.
    __shared__ float s_c[36];
    __shared__ float s_s[36];

    const int tid = threadIdx.x;
    const int p   = blockIdx.x >> 2;
    const int q   = blockIdx.x & 3;
    const int k0  = q << 4;              // first row-group of this chunk
    const int off = 2 * k0 - 1;

    // Phase 1a: table slice (2 warps of heavy math; overlaps with the zero
    // stores below — no table dependence until after the sync).
    if (tid < 36) {
        const int i = off + tid;
        if (i >= 0 && i < K_ITERS) {
            const double e = -2.0 * ((double)i - 1.0) / 256.0;
            const float theta = (float)exp(e * 9.210340371976184);  // ln(10000)
            const float m = (float)p * theta;
            s_s[tid] = sinf(m);
            s_c[tid] = cosf(m);
        }
    }

    // Patch ownership (index math only). ka/kb = row-group-within-chunk of the
    // quads this thread patches in phase 2; -1 = none.
    const int h = tid >> 6;
    const int j = tid & 63;
    const int k1 = k0 + 16;
    int ka = -1, kb = -1;
    if (h == 0) {
        if (j >= k0 && j < k1)                     ka = j - k0;       // row 4j, quad j
        if (j <= 62 && (j + 1) >= k0 && (j + 1) < k1) kb = j + 1 - k0; // row 4j+4, quad j
    } else if (h == 2) {
        if (j >= k0 && j < k1)                     ka = j - k0;       // row 4j+2, quad j
        if (j >= 1 && (j - 1) >= k0 && (j - 1) < k1)  kb = j - 1 - k0; // row 4j-2, quad j
    }

    // Phase 1b: stream zeros for this chunk, skipping the patch quads.
    float4* mbase = out + ((size_t)p << 14) + tid;        // matrix base + tid
    float4* zbase = mbase + ((size_t)k0 << 8);            // chunk base
    const float4 z = make_float4(0.f, 0.f, 0.f, 0.f);
#pragma unroll
    for (int k = 0; k < 16; k++) {
        if (k != ka && k != kb)
            zbase[k << 8] = z;           // STG.E.128 [R + k*4096], zeros
    }

    __syncthreads();

    // Phase 2: write the patch quads (exactly once each).
#define SSx(i) s_s[(i) - off]
#define SCx(i) s_c[(i) - off]
    if (h == 0) {
        if (ka >= 0)   // row 4j, quad j: .x = cos_{2j}, .z = -sin_{2j}
            mbase[j << 8] = make_float4(SCx(2 * j), 0.f, -SSx(2 * j), 0.f);
        if (kb >= 0)   // row 4j+4, quad j: .z = sin_{2j+1}
            mbase[(j + 1) << 8] = make_float4(0.f, 0.f, SSx(2 * j + 1), 0.f);
    } else if (h == 2) {
        if (ka >= 0) { // row 4j+2, quad j: .x = sin_{2j}, .z = cos_{min(2j+1,126)}
            int i = 2 * j + 1; if (i > K_ITERS - 1) i = K_ITERS - 1;
            mbase[j << 8] = make_float4(SSx(2 * j), 0.f, SCx(i), 0.f);
        }
        if (kb >= 0)   // row 4j-2, quad j: .x = -sin_{2j-1}
            mbase[(j - 1) << 8] = make_float4(-SSx(2 * j - 1), 0.f, 0.f, 0.f);
    }
#undef SSx
#undef SCx
}

extern "C" void kernel_launch(void* const* d_in, const int* in_sizes, int n_in,
                              void* d_out, int out_size) {
    (void)d_in; (void)in_sizes; (void)n_in; (void)out_size;
    rope_kernel<<<8192, 256, 0, 0>>>((float4*)d_out);
}

// round 8
// speedup vs baseline: 1.3933x; 1.3933x over previous
#include <cuda_runtime.h>
#include <cuda_bf16.h>
#include <math.h>

// Static shapes: B=2048, D=256, K = D/2-1 = 127. Output R[2048,256,256] fp32.
// Nonzeros (even rows r only):
//   col r-2 -> sin(p*theta_{(r-2)/2})    (r >= 2)
//   col r   -> cos(p*theta_{min(r/2,126)})
//   col r+2 -> -sin(p*theta_{r/2})       (r/2 <= 126)
// theta_i = 10000^(-2*(i-1)/256)
//
// Grid: 8192 blocks = 2048 matrices x 4 chunks. Chunk q owns row-groups
// kp in [16q, 16q+16) (each group = 4 rows = 256 quads). Thread tid = h*64+j
// writes quad (kp*256 + tid) for each kp in its chunk: 16 warp-uniform
// STG.128 of zeros, then <=2 patch STG.128 overwriting the near-diagonal
// quads (same thread, same address -> program order, patch wins).
//
// R8 = exact revert to the best-measured R5 configuration. R6 (cache-policy
// A/B) was neutral; R7 (skip-the-patch-quads) fragmented warp stores and
// regressed 40% — full-width double-write is the right trade.

#define K_ITERS 127

__global__ __launch_bounds__(256) void rope_kernel(float4* __restrict__ out) {
    // Table slice: indices i = off + t, t in [0,36), off = 2*k0 - 1.
    __shared__ float s_c[36];
    __shared__ float s_s[36];

    const int tid = threadIdx.x;
    const int p   = blockIdx.x >> 2;
    const int q   = blockIdx.x & 3;
    const int k0  = q << 4;              // first row-group of this chunk
    const int off = 2 * k0 - 1;

    // Phase 1a: table slice (2 warps of heavy math; overlaps with zeros below).
    if (tid < 36) {
        const int i = off + tid;
        if (i >= 0 && i < K_ITERS) {
            const double e = -2.0 * ((double)i - 1.0) / 256.0;
            const float theta = (float)exp(e * 9.210340371976184);  // ln(10000)
            const float m = (float)p * theta;
            s_s[tid] = sinf(m);
            s_c[tid] = cosf(m);
        }
    }

    // Phase 1b: stream zeros for this chunk (no dependence on the table).
    float4* mbase = out + ((size_t)p << 14) + tid;        // matrix base + tid
    float4* zbase = mbase + ((size_t)k0 << 8);            // chunk base
    const float4 z = make_float4(0.f, 0.f, 0.f, 0.f);
#pragma unroll
    for (int k = 0; k < 16; k++) {
        __stcs(&zbase[k << 8], z);       // STG.E.128.CS [R + k*4096], zeros
    }

    __syncthreads();

    // Phase 2: patches. SSx/SCx index the slice.
#define SSx(i) s_s[(i) - off]
#define SCx(i) s_c[(i) - off]
    const int h = tid >> 6;
    const int j = tid & 63;
    const int k1 = k0 + 16;
    if (h == 0) {
        // row 4j, quad j: .x = cos_{2j}, .z = -sin_{2j}
        if (j >= k0 && j < k1)
            mbase[j << 8] = make_float4(SCx(2 * j), 0.f, -SSx(2 * j), 0.f);
        // row 4j+4, quad j: .z = sin_{2j+1}
        if (j <= 62 && (j + 1) >= k0 && (j + 1) < k1)
            mbase[(j + 1) << 8] = make_float4(0.f, 0.f, SSx(2 * j + 1), 0.f);
    } else if (h == 2) {
        // row 4j+2, quad j: .x = sin_{2j}, .z = cos_{min(2j+1,126)}
        if (j >= k0 && j < k1) {
            int i = 2 * j + 1; if (i > K_ITERS - 1) i = K_ITERS - 1;
            mbase[j << 8] = make_float4(SSx(2 * j), 0.f, SCx(i), 0.f);
        }
        // row 4j-2, quad j: .x = -sin_{2j-1}
        if (j >= 1 && (j - 1) >= k0 && (j - 1) < k1)
            mbase[(j - 1) << 8] = make_float4(-SSx(2 * j - 1), 0.f, 0.f, 0.f);
    }
#undef SSx
#undef SCx
}

extern "C" void kernel_launch(void* const* d_in, const int* in_sizes, int n_in,
                              void* d_out, int out_size) {
    (void)d_in; (void)in_sizes; (void)n_in; (void)out_size;
    rope_kernel<<<8192, 256, 0, 0>>>((float4*)d_out);
}